// round 2
// baseline (speedup 1.0000x reference)
#include <cuda_runtime.h>
#include <cstdint>

#define NN 8192
#define DIN 256
#define DOUT 32
#define NPOOL 128

// ---------------- scratch (device globals) ----------------
__device__ float    g_support[NN * DOUT];
__device__ float    g_logits[NN * DOUT];
__device__ unsigned g_colmax_bits[DOUT];
__device__ float    g_colmax_f[DOUT];
__device__ float    g_colinv[DOUT];
__device__ float    g_sumpart[NPOOL * DOUT];
__device__ float    g_part[NPOOL * DOUT * DIN];

// ---------------- packed fp32x2 (FFMA2) helpers ----------------
__device__ __forceinline__ unsigned long long pack2(float x) {
    unsigned long long r;
    asm("mov.b64 %0, {%1, %1};" : "=l"(r) : "f"(x));
    return r;
}
__device__ __forceinline__ unsigned long long ffma2(unsigned long long a,
                                                    unsigned long long b,
                                                    unsigned long long c) {
    unsigned long long d;
    asm("fma.rn.f32x2 %0, %1, %2, %3;" : "=l"(d) : "l"(a), "l"(b), "l"(c));
    return d;
}
__device__ __forceinline__ float2 unpack2(unsigned long long v) {
    float2 f;
    asm("mov.b64 {%0, %1}, %2;" : "=f"(f.x), "=f"(f.y) : "l"(v));
    return f;
}

// monotone float->uint key (order-preserving, works for all signs)
__device__ __forceinline__ unsigned fkey(float f) {
    int b = __float_as_int(f);
    return (unsigned)(b ^ ((b >> 31) | 0x80000000));
}
__device__ __forceinline__ float funkey(unsigned u) {
    int b = (u & 0x80000000u) ? (int)(u ^ 0x80000000u) : ~(int)u;
    return __int_as_float(b);
}

// ---------------------------------------------------------------------------
// C[M x 32] = A[M x K] @ S[K x 32]
// 256 CTAs x 32 rows, 8 warps split K 8-way (chunks of 32 k).
// Per-warp SMEM: a_buf[32k][33] transposed+padded, s_buf[32k][32c].
// launch_bounds(256,2) -> 2 CTAs/SM -> 4 warps/SMSP for latency hiding.
// Optional epilogue: per-column max -> global atomicMax (order-independent,
// deterministic). Cross-warp reduce is fixed-order -> deterministic.
// ---------------------------------------------------------------------------
#define ROWS 32
#define ABUF_STRIDE (32 * 33)
#define SBUF_BASE   (8 * ABUF_STRIDE)
#define GEMM_SMEM_BYTES ((SBUF_BASE + 8 * 32 * 32) * 4)   // 66560 B

__global__ void __launch_bounds__(256, 2)
gemm_n32_kernel(const float* __restrict__ A, const float* __restrict__ S,
                float* __restrict__ C, int K, int do_max, int do_init)
{
    extern __shared__ float smem[];
    __shared__ unsigned smax[DOUT];
    const int t  = threadIdx.x;
    const int w  = t >> 5;
    const int l  = t & 31;
    const int rb = blockIdx.x * ROWS;

    if (do_init && blockIdx.x == 0 && t < DOUT) g_colmax_bits[t] = 0u;
    if (do_max && t < DOUT) smax[t] = 0u;

    float* a_buf = smem + w * ABUF_STRIDE;
    float* s_buf = smem + SBUF_BASE + w * (32 * 32);

    const int kslice = K >> 3;
    const int nchunk = kslice >> 5;
    const int k0 = w * kslice;

    unsigned long long acc[16];
#pragma unroll
    for (int i = 0; i < 16; i++) acc[i] = 0ull;

    for (int ch = 0; ch < nchunk; ch++) {
        const int kc = k0 + ch * 32;
        __syncwarp();
        // stage A: 32 rows x 32 k -> transposed [k][row] pad-33 (conflict-free)
#pragma unroll
        for (int j = 0; j < 8; j++) {
            int f   = j * 32 + l;
            int row = f >> 3;
            int k4  = (f & 7) << 2;
            float4 v = *reinterpret_cast<const float4*>(
                A + (size_t)(rb + row) * K + kc + k4);
            a_buf[(k4 + 0) * 33 + row] = v.x;
            a_buf[(k4 + 1) * 33 + row] = v.y;
            a_buf[(k4 + 2) * 33 + row] = v.z;
            a_buf[(k4 + 3) * 33 + row] = v.w;
        }
        // stage S: 32 k x 32 c, contiguous
#pragma unroll
        for (int j = 0; j < 8; j++) {
            int f = j * 32 + l;
            *reinterpret_cast<float4*>(s_buf + f * 4) =
                *reinterpret_cast<const float4*>(S + (size_t)kc * 32 + f * 4);
        }
        __syncwarp();
        // compute: lane owns row l, all 32 cols (16 f32x2 accumulators)
#pragma unroll 4
        for (int k = 0; k < 32; k++) {
            unsigned long long a0 = pack2(a_buf[k * 33 + l]);
            const ulonglong2* s2 =
                reinterpret_cast<const ulonglong2*>(s_buf + k * 32);
#pragma unroll
            for (int c = 0; c < 8; c++) {
                ulonglong2 sv = s2[c];               // LDS.128 broadcast
                acc[2 * c]     = ffma2(a0, sv.x, acc[2 * c]);
                acc[2 * c + 1] = ffma2(a0, sv.y, acc[2 * c + 1]);
            }
        }
    }

    // ---- cross-warp fixed-order reduce ----
    __syncthreads();
    float* red = smem;   // overlay [8][32][33] = 33792 B
#pragma unroll
    for (int c = 0; c < 16; c++) {
        float2 v = unpack2(acc[c]);
        red[(w * 32 + l) * 33 + 2 * c]     = v.x;
        red[(w * 32 + l) * 33 + 2 * c + 1] = v.y;
    }
    __syncthreads();
    {
        int row = t >> 3;
        int c0  = (t & 7) * 4;
        float r[4] = {0.f, 0.f, 0.f, 0.f};
#pragma unroll
        for (int ww = 0; ww < 8; ww++) {
            const float* p = red + (ww * 32 + row) * 33 + c0;
#pragma unroll
            for (int i = 0; i < 4; i++) r[i] += p[i];
        }
        *reinterpret_cast<float4*>(C + (size_t)(rb + row) * 32 + c0) =
            make_float4(r[0], r[1], r[2], r[3]);

        if (do_max) {
#pragma unroll
            for (int i = 0; i < 4; i++)
                atomicMax(&smax[c0 + i], fkey(r[i]));
        }
    }
    if (do_max) {
        __syncthreads();
        if (t < DOUT) atomicMax(&g_colmax_bits[t], smax[t]);
    }
}

// ---------------------------------------------------------------------------
// Partial exp-sums per 64-row block (coalesced reads, fixed-order col reduce)
// ---------------------------------------------------------------------------
__global__ void __launch_bounds__(256, 2)
expsum_kernel()
{
    __shared__ float sred[64 * 33];
    __shared__ float cmax[DOUT];
    const int t  = threadIdx.x;
    const int rb = blockIdx.x * 64;

    if (t < DOUT) cmax[t] = funkey(g_colmax_bits[t]);
    __syncthreads();

    const int row = t >> 2;
    const int c0  = (t & 3) * 8;
#pragma unroll
    for (int h = 0; h < 2; h++) {
        float4 v = *reinterpret_cast<const float4*>(
            g_logits + (size_t)(rb + row) * DOUT + c0 + h * 4);
        sred[row * 33 + c0 + h * 4 + 0] = __expf(v.x - cmax[c0 + h * 4 + 0]);
        sred[row * 33 + c0 + h * 4 + 1] = __expf(v.y - cmax[c0 + h * 4 + 1]);
        sred[row * 33 + c0 + h * 4 + 2] = __expf(v.z - cmax[c0 + h * 4 + 2]);
        sred[row * 33 + c0 + h * 4 + 3] = __expf(v.w - cmax[c0 + h * 4 + 3]);
    }
    __syncthreads();
    if (t < DOUT) {
        float s = 0.f;
#pragma unroll 8
        for (int r = 0; r < 64; r++) s += sred[r * 33 + t];
        g_sumpart[blockIdx.x * DOUT + t] = s;
    }
}

__global__ void colinv_kernel()
{
    const int c = threadIdx.x;   // 32
    float s = 0.f;
#pragma unroll 8
    for (int b = 0; b < NPOOL; b++) s += g_sumpart[b * DOUT + c];
    g_colinv[c]  = 1.0f / s;
    g_colmax_f[c] = funkey(g_colmax_bits[c]);
}

// ---------------------------------------------------------------------------
// Pooling partials: part[blk][c][d] = sum_{i in blk} softmax(i,c) * X[i][d]
// 128 CTAs x 64 rows; thread t = feature d. Row loop unrolled x8 with
// up-front independent LDGs (MLP 8) to kill the serial-latency stall.
// ---------------------------------------------------------------------------
__global__ void __launch_bounds__(256, 2)
pool_kernel(const float* __restrict__ X)
{
    __shared__ float wsm[64 * DOUT];
    const int t  = threadIdx.x;
    const int rb = blockIdx.x * 64;

#pragma unroll
    for (int q = 0; q < 8; q++) {
        int idx = t * 8 + q;
        int il  = idx >> 5;
        int c   = idx & 31;
        float lg = g_logits[(size_t)(rb + il) * DOUT + c];
        wsm[idx] = __expf(lg - g_colmax_f[c]) * g_colinv[c];
    }
    __syncthreads();

    unsigned long long acc[16];
#pragma unroll
    for (int i = 0; i < 16; i++) acc[i] = 0ull;

    for (int g = 0; g < 8; g++) {
        float xv[8];
#pragma unroll
        for (int q = 0; q < 8; q++)
            xv[q] = X[(size_t)(rb + g * 8 + q) * DIN + t];   // 8 indep LDGs
#pragma unroll
        for (int q = 0; q < 8; q++) {
            unsigned long long xp = pack2(xv[q]);
            const ulonglong2* wv =
                reinterpret_cast<const ulonglong2*>(wsm + (g * 8 + q) * DOUT);
#pragma unroll
            for (int c = 0; c < 8; c++) {
                ulonglong2 sv = wv[c];
                acc[2 * c]     = ffma2(xp, sv.x, acc[2 * c]);
                acc[2 * c + 1] = ffma2(xp, sv.y, acc[2 * c + 1]);
            }
        }
    }

    float* pp = g_part + (size_t)blockIdx.x * (DOUT * DIN);
#pragma unroll
    for (int c = 0; c < 16; c++) {
        float2 v = unpack2(acc[c]);
        pp[(2 * c) * DIN + t]     = v.x;
        pp[(2 * c + 1) * DIN + t] = v.y;
    }
}

// ---------------------------------------------------------------------------
__global__ void reduce_out_kernel(float* __restrict__ out)
{
    const int c = blockIdx.x;     // 32
    const int t = threadIdx.x;    // 256
    float s = 0.0f;
#pragma unroll 8
    for (int b = 0; b < NPOOL; b++)
        s += g_part[(size_t)b * (DOUT * DIN) + c * DIN + t];
    out[c * DIN + t] = s;
}

// ---------------------------------------------------------------------------
extern "C" void kernel_launch(void* const* d_in, const int* in_sizes, int n_in,
                              void* d_out, int out_size)
{
    const float* X = (const float*)d_in[0];   // main_feat [8192,256]
    const float* A = (const float*)d_in[1];   // main_adj  [8192,8192]
    const float* W = (const float*)d_in[2];   // W         [256,32]
    // d_in[3] = b: per-column constant -> softmax over axis 0 invariant -> dropped
    float* out = (float*)d_out;

    float *sup, *logits;
    cudaGetSymbolAddress((void**)&sup, g_support);
    cudaGetSymbolAddress((void**)&logits, g_logits);

    cudaFuncSetAttribute(gemm_n32_kernel,
                         cudaFuncAttributeMaxDynamicSharedMemorySize,
                         GEMM_SMEM_BYTES);

    // 1) support = X @ W  (+ zero colmax accumulator from CTA 0)
    gemm_n32_kernel<<<NN / ROWS, 256, GEMM_SMEM_BYTES>>>(X, W, sup, DIN, 0, 1);
    // 2) logits = A @ support  (+ fused per-column max epilogue)
    gemm_n32_kernel<<<NN / ROWS, 256, GEMM_SMEM_BYTES>>>(A, sup, logits, NN, 1, 0);
    // 3) partial exp-sums (coalesced)
    expsum_kernel<<<NPOOL, 256>>>();
    // 4) 1/sum + decoded max
    colinv_kernel<<<1, DOUT>>>();
    // 5) weighted pooling partials
    pool_kernel<<<NPOOL, 256>>>(X);
    // 6) deterministic final reduce
    reduce_out_kernel<<<DOUT, 256>>>(out);
}